// round 7
// baseline (speedup 1.0000x reference)
#include <cuda_runtime.h>
#include <cstdint>

#define N     8192
#define K1    31
#define CAP   256      // per-line candidate capacity (mean 88, max ~135)
#define PIVOT 2.3f     // P(z>2.3)=0.0107
#define NF4   ((size_t)N * N / 4)
#define FULLM 0xFFFFFFFFu

__device__ unsigned int       g_bits[(size_t)N * N / 32];  // 8 MB candidate bitmask
__device__ unsigned long long g_colcand[(size_t)N * CAP];  // 16 MB
__device__ int                g_colcnt[N];
__device__ unsigned long long g_rowth[N];

// Monotone map float -> uint32 (larger float => larger key)
__device__ __forceinline__ unsigned int fkey(float x) {
    unsigned int u = __float_as_uint(x);
    return (u & 0x80000000u) ? ~u : (u | 0x80000000u);
}
__device__ __forceinline__ float inv_fkey(unsigned int k) {
    unsigned int u = (k & 0x80000000u) ? (k ^ 0x80000000u) : ~k;
    return __uint_as_float(u);
}
// Composite key: value-major, lower index wins ties (stable top_k semantics)
__device__ __forceinline__ unsigned long long ckey(float x, int idx) {
    return ((unsigned long long)fkey(x) << 32) | (unsigned int)(N - 1 - idx);
}

__device__ __forceinline__ unsigned long long warp_max(unsigned long long v) {
#pragma unroll
    for (int o = 16; o > 0; o >>= 1) {
        unsigned long long w = __shfl_xor_sync(FULLM, v, o);
        if (w > v) v = w;
    }
    return v;
}

// warp-level exact fallback: K1-th largest composite key of a full line
template <bool ROW>
__device__ unsigned long long warp_fallback(const float* __restrict__ A, int line, int lane) {
    unsigned long long prev = 0xFFFFFFFFFFFFFFFFull;
    for (int it = 0; it < K1; it++) {
        unsigned long long best = 0;
        for (int t = lane; t < N; t += 32) {
            float x = ROW ? A[(size_t)line * N + t] : A[(size_t)t * N + line];
            unsigned long long k = ckey(x, t);
            if (k < prev && k > best) best = k;
        }
        prev = warp_max(best);
    }
    return prev;
}

// K1: PURE streaming pass. Reads A, writes zeros to out, emits candidate
// bitmask via warp ballots. First 32 blocks also zero g_colcnt.
// Word wi (within row), bit b  <->  element (wi>>2)*128 + b*4 + (wi&3).
__global__ __launch_bounds__(256) void stream_kernel(const float* __restrict__ A,
                                                     float* __restrict__ out) {
    if (blockIdx.x < N / 256) g_colcnt[blockIdx.x * 256 + threadIdx.x] = 0;
    const size_t g = (size_t)blockIdx.x * 256 + threadIdx.x;  // float4 index
    float4 v = ((const float4*)A)[g];
    const float4 zz = {0.0f, 0.0f, 0.0f, 0.0f};
    ((float4*)out)[g] = zz;
    unsigned m0 = __ballot_sync(FULLM, v.x > PIVOT);
    unsigned m1 = __ballot_sync(FULLM, v.y > PIVOT);
    unsigned m2 = __ballot_sync(FULLM, v.z > PIVOT);
    unsigned m3 = __ballot_sync(FULLM, v.w > PIVOT);
    if ((threadIdx.x & 31) == 0) {
        uint4 w = {m0, m1, m2, m3};
        ((uint4*)g_bits)[g >> 5] = w;
    }
}

// K2: warp per row (8 rows per CTA). Decode bitmask -> gather candidates,
// push column candidates, compute g_rowth by rank-counting. No block barriers.
__global__ __launch_bounds__(256) void rowth_kernel(const float* __restrict__ A) {
    const int w = threadIdx.x >> 5, lane = threadIdx.x & 31;
    const int i = blockIdx.x * 8 + w;
    __shared__ unsigned long long scap[8][CAP];

    unsigned wrd[8];
    int cnt = 0;
#pragma unroll
    for (int idx = 0; idx < 8; idx++) {
        wrd[idx] = g_bits[(size_t)i * 256 + idx * 32 + lane];
        cnt += __popc(wrd[idx]);
    }
    // warp inclusive scan -> exclusive offset
    int off = cnt;
#pragma unroll
    for (int d = 1; d < 32; d <<= 1) {
        int v = __shfl_up_sync(FULLM, off, d);
        if (lane >= d) off += v;
    }
    const int total = __shfl_sync(FULLM, off, 31);
    off -= cnt;

    const bool ok = (total >= K1 && total <= CAP);
#pragma unroll
    for (int idx = 0; idx < 8; idx++) {
        unsigned wb = wrd[idx];
        const int wi = idx * 32 + lane;
        const int seg = wi >> 2, comp = wi & 3;
        while (wb) {
            int b = __ffs(wb) - 1;
            wb &= wb - 1;
            int j = seg * 128 + b * 4 + comp;
            float x = A[(size_t)i * N + j];
            if (ok && off < CAP) scap[w][off] = ckey(x, j);
            off++;
            int cs = atomicAdd(&g_colcnt[j], 1);
            if (cs < CAP) g_colcand[(size_t)j * CAP + cs] = ckey(x, i);
        }
    }
    __syncwarp();

    if (ok) {
        // reload in slot layout: lane owns slots lane, lane+32, ...
        unsigned long long myk[8];
        int rk[8];
        const int nq = (total + 31) >> 5;
#pragma unroll
        for (int q = 0; q < 8; q++) {
            int s = q * 32 + lane;
            myk[q] = (q < nq && s < total) ? scap[w][s] : 0ull;
            rk[q] = 0;
        }
        for (int m = 0; m < total; m++) {
            unsigned long long km = scap[w][m];   // LDS broadcast
#pragma unroll
            for (int q = 0; q < 8; q++) rk[q] += (km > myk[q]);
        }
        unsigned long long th = 0;
#pragma unroll
        for (int q = 0; q < 8; q++) {
            int s = q * 32 + lane;
            if (q < nq && s < total && rk[q] == K1 - 1) th = myk[q];
        }
        th = warp_max(th);
        if (lane == 0) g_rowth[i] = th;
    } else {
        unsigned long long th = warp_fallback<true>(A, i, lane);
        if (lane == 0) g_rowth[i] = th;
    }
}

// K3: warp per column (8 cols per CTA). Column threshold by shuffle
// rank-counting, then scatter survivors. Register-resident, no barriers.
__global__ __launch_bounds__(256) void colth_scatter_kernel(const float* __restrict__ A,
                                                            float* __restrict__ out) {
    const int w = threadIdx.x >> 5, lane = threadIdx.x & 31;
    const int j = blockIdx.x * 8 + w;
    const int c = g_colcnt[j];

    if (c >= K1 && c <= CAP) {
        unsigned long long kq[8];
        int rk[8];
        const int nq = (c + 31) >> 5;
#pragma unroll
        for (int q = 0; q < 8; q++) {
            int s = q * 32 + lane;
            kq[q] = (q < nq && s < c) ? g_colcand[(size_t)j * CAP + s] : 0ull;
            rk[q] = 0;
        }
#pragma unroll
        for (int q2 = 0; q2 < 8; q2++) {
            if (q2 >= nq) break;
            for (int src = 0; src < 32; src++) {
                unsigned long long km = __shfl_sync(FULLM, kq[q2], src);
                if (q2 * 32 + src < c) {
#pragma unroll
                    for (int q = 0; q < 8; q++) rk[q] += (km > kq[q]);
                }
            }
        }
        unsigned long long cth = 0;
#pragma unroll
        for (int q = 0; q < 8; q++) {
            int s = q * 32 + lane;
            if (q < nq && s < c && rk[q] == K1 - 1) cth = kq[q];
        }
        cth = warp_max(cth);
        // scatter survivors of column j
#pragma unroll
        for (int q = 0; q < 8; q++) {
            int s = q * 32 + lane;
            if (q < nq && s < c && kq[q] >= cth) {
                int i = N - 1 - (int)(unsigned int)(kq[q] & 0xFFFFFFFFu);
                if (i != j) {
                    float x = inv_fkey((unsigned int)(kq[q] >> 32));
                    if (ckey(x, j) >= g_rowth[i])
                        out[(size_t)i * N + j] = x;
                }
            }
        }
    } else {
        // exact threshold + full-column rescan for coverage
        unsigned long long cth = warp_fallback<false>(A, j, lane);
        for (int i = lane; i < N; i += 32) {
            if (i == j) continue;
            float x = A[(size_t)i * N + j];
            if (ckey(x, i) >= cth && ckey(x, j) >= g_rowth[i])
                out[(size_t)i * N + j] = x;
        }
    }
}

extern "C" void kernel_launch(void* const* d_in, const int* in_sizes, int n_in,
                              void* d_out, int out_size) {
    const float* A = (const float*)d_in[0];
    float* out = (float*)d_out;
    stream_kernel<<<(unsigned)(NF4 / 256), 256>>>(A, out);
    rowth_kernel<<<N / 8, 256>>>(A);
    colth_scatter_kernel<<<N / 8, 256>>>(A, out);
}